// round 16
// baseline (speedup 1.0000x reference)
#include <cuda_runtime.h>
#include <math.h>

// Problem constants: NS = NT = 80, D = 512, N = 6400, kdiag = 79*79 = 6241.
#define NSd   80
#define Dd    512
#define Nn    6400
#define GPERS 148   // persistent grid; launch_bounds(256,2) guarantees co-residency

typedef unsigned long long u64t;

// Packed fp32x2 FMA (Blackwell): one fma-pipe issue = 2 IEEE fp32 FMAs.
__device__ __forceinline__ u64t ffma2(u64t a, u64t b, u64t c) {
    u64t d;
    asm("fma.rn.f32x2 %0, %1, %2, %3;" : "=l"(d) : "l"(a), "l"(b), "l"(c));
    return d;
}
__device__ __forceinline__ u64t pack2(float x) {
    u64t d;
    asm("mov.b64 %0, {%1, %1};" : "=l"(d) : "f"(x));
    return d;
}

// fp32 -> tf32 (round-to-nearest) as raw b32.
__device__ __forceinline__ unsigned f2tf(float x) {
    unsigned u;
    asm("cvt.rna.tf32.f32 %0, %1;" : "=r"(u) : "f"(x));
    return u;
}

// D += A(16x8, tf32, row) * B(8x8, tf32, col);  fp32 accumulate.
__device__ __forceinline__ void mma_tf32(float* d, const unsigned* a,
                                         unsigned b0, unsigned b1) {
    asm("mma.sync.aligned.m16n8k8.row.col.f32.tf32.tf32.f32 "
        "{%0,%1,%2,%3}, {%4,%5,%6,%7}, {%8,%9}, {%0,%1,%2,%3};"
        : "+f"(d[0]), "+f"(d[1]), "+f"(d[2]), "+f"(d[3])
        : "r"(a[0]), "r"(a[1]), "r"(a[2]), "r"(a[3]), "r"(b0), "r"(b1));
}

// ---------------- device scratch (no allocation allowed) ----------------
__device__ float g_e1[NSd * Dd];
__device__ float g_e2[NSd * Dd];
__device__ float g_m1[NSd * Dd];
__device__ float g_m2[NSd * Dd];
__device__ float g_x1[NSd * Dd];
__device__ float g_x2[NSd * Dd];
__device__ float g_y1[NSd * Dd];
__device__ float g_y2[NSd * Dd];
__device__ float g_Mp0[NSd * NSd];
__device__ float g_v[Nn];             // v[p] = Mp[p%80, p/80]
__device__ float g_inv[64 * 64];      // invL of current diag block
__device__ int   g_cnt = 0;           // grid barrier arrival counter (self-restoring)
__device__ int   g_gen = 0;           // grid barrier generation (monotonic; compared relatively)

__device__ __forceinline__ float warp_sum(float s) {
#pragma unroll
    for (int o = 16; o > 0; o >>= 1) s += __shfl_xor_sync(0xffffffffu, s, o);
    return s;
}

__device__ __forceinline__ void grid_sync() {
    __threadfence();
    __syncthreads();
    if (threadIdx.x == 0) {
        int gen = atomicAdd(&g_gen, 0);
        if (atomicAdd(&g_cnt, 1) == (int)gridDim.x - 1) {
            g_cnt = 0;
            __threadfence();
            atomicExch(&g_gen, gen + 1);
        } else {
            while (atomicAdd(&g_gen, 0) == gen) { }
        }
    }
    __syncthreads();
}

// ---------------- Cholesky building blocks ----------------

// Factor 64x64 block at A (ld = Nn) in place (lower); write invL into g_inv.
__device__ void fact64(float* __restrict__ A, float* __restrict__ sbuf) {
    float* Lsh    = sbuf;            // 64*65
    float* colbuf = sbuf + 64 * 65;  // 64
    int tid = threadIdx.x;

    for (int idx = tid; idx < 64 * 64; idx += 256) {
        int r = idx >> 6, c = idx & 63;
        if (c <= r) Lsh[r * 65 + c] = A[(size_t)r * Nn + c];
    }
    __syncthreads();

    int tq = tid & 63, trow = tid >> 6;
    for (int c = 0; c < 64; c++) {
        if (tid < 64) colbuf[tid] = Lsh[tid * 65 + c];
        __syncthreads();
        float dv  = sqrtf(colbuf[c]);
        float inv = 1.0f / dv;
        float i2  = inv * inv;
        if (tid < 64) {
            if (tid > c)       Lsh[tid * 65 + c] = colbuf[tid] * inv;
            else if (tid == c) Lsh[c * 65 + c]   = dv;
        }
        if (tq > c) {
            float xq = colbuf[tq] * i2;
            for (int rr = c + 1 + trow; rr < 64; rr += 4)
                Lsh[rr * 65 + tq] -= colbuf[rr] * xq;
        }
        __syncthreads();
    }

    for (int idx = tid; idx < 64 * 64; idx += 256) {
        int r = idx >> 6, c = idx & 63;
        if (c <= r) A[(size_t)r * Nn + c] = Lsh[r * 65 + c];
    }

    if (tid < 64) colbuf[tid] = 1.0f / Lsh[tid * 65 + tid];
    __syncthreads();

    if (tid < 64) {
        int c = tid;
        float x[64];
        x[c] = colbuf[c];
        for (int jj = c + 1; jj < 64; jj++) {
            float s0 = 0.f, s1 = 0.f, s2 = 0.f, s3 = 0.f;
            int k = c;
            for (; k + 3 < jj; k += 4) {
                s0 += Lsh[jj * 65 + k + 0] * x[k + 0];
                s1 += Lsh[jj * 65 + k + 1] * x[k + 1];
                s2 += Lsh[jj * 65 + k + 2] * x[k + 2];
                s3 += Lsh[jj * 65 + k + 3] * x[k + 3];
            }
            for (; k < jj; k++) s0 += Lsh[jj * 65 + k] * x[k];
            x[jj] = -((s0 + s1) + (s2 + s3)) * colbuf[jj];
        }
        for (int jj = 0; jj < 64; jj++)
            g_inv[jj * 64 + c] = (jj >= c) ? x[jj] : 0.f;
    }
    __syncthreads();
}

// Panel solve tile: X = B * invL^T for 64 rows at row0 (in place), step j.
// 256 threads, 2x8 micro-tile, packed f32x2 FMA (exact fp32).
__device__ void trsm64_tile(float* __restrict__ L, int j, int M, int row0,
                            float* __restrict__ sbuf) {
    float (*As)[68] = (float(*)[68])sbuf;
    float (*Bs)[68] = (float(*)[68])(sbuf + 16 * 68);
    float* B = L + (size_t)(j + 64) * Nn + j;
    int tid = threadIdx.x;

    u64t acc2[2][4];
#pragma unroll
    for (int u = 0; u < 2; u++)
#pragma unroll
        for (int v = 0; v < 4; v++) acc2[u][v] = 0ull;

    int ty = tid >> 3, tx = tid & 7;       // ty 0..31, tx 0..7
    int rr = ty * 2, cc = tx * 8;
    int li  = tid >> 2;                    // 0..63
    int lk4 = (tid & 3) << 2;

    for (int kk = 0; kk < 64; kk += 16) {
        float4 av = make_float4(0.f, 0.f, 0.f, 0.f);
        if (row0 + li < M)
            av = *(const float4*)(B + (size_t)(row0 + li) * Nn + kk + lk4);
        float4 bv = *(const float4*)(g_inv + li * 64 + kk + lk4);
        __syncthreads();
        As[lk4 + 0][li] = av.x; As[lk4 + 1][li] = av.y;
        As[lk4 + 2][li] = av.z; As[lk4 + 3][li] = av.w;
        Bs[lk4 + 0][li] = bv.x; Bs[lk4 + 1][li] = bv.y;
        Bs[lk4 + 2][li] = bv.z; Bs[lk4 + 3][li] = bv.w;
        __syncthreads();
#pragma unroll
        for (int k = 0; k < 16; k++) {
            u64t a0 = pack2(As[k][rr]);
            u64t a1 = pack2(As[k][rr + 1]);
            union { float4 f4[2]; u64t u2[4]; } bq;
            bq.f4[0] = *(const float4*)&Bs[k][cc];
            bq.f4[1] = *(const float4*)&Bs[k][cc + 4];
#pragma unroll
            for (int v = 0; v < 4; v++) {
                acc2[0][v] = ffma2(a0, bq.u2[v], acc2[0][v]);
                acc2[1][v] = ffma2(a1, bq.u2[v], acc2[1][v]);
            }
        }
    }
    __syncthreads();
#pragma unroll
    for (int u = 0; u < 2; u++) {
        int gr = row0 + rr + u;
        if (gr < M) {
            union { u64t u2[4]; float4 f4[2]; } r;
#pragma unroll
            for (int v = 0; v < 4; v++) r.u2[v] = acc2[u][v];
            float* bp = B + (size_t)gr * Nn + cc;
            *(float4*)bp       = r.f4[0];
            *(float4*)(bp + 4) = r.f4[1];
        }
    }
}

// Trailing-update tile: C(128x128 at by,bx) -= P*P^T.
// Tensor-core path: mma.sync m16n8k8 tf32, fp32 accumulate.
// Warp w covers rows (w>>1)*32, cols (w&1)*64 of the tile (2 m-frags x 8 n-frags).
__device__ void syrk_tile(float* __restrict__ L, int j, int M, int bx, int by,
                          float* __restrict__ sbuf) {
    float (*As)[136] = (float(*)[136])sbuf;
    float (*Bs)[136] = (float(*)[136])(sbuf + 16 * 136);
    const float* P = L + (size_t)(j + 64) * Nn + j;
    float* C       = L + (size_t)(j + 64) * Nn + (j + 64);
    int row0 = by * 128, col0 = bx * 128;
    int tid = threadIdx.x;
    int lane = tid & 31, wid = tid >> 5;
    int gidx = lane >> 2;            // groupID 0..7
    int tig  = lane & 3;             // thread-in-group 0..3
    int row_g = (wid >> 1) * 32;     // warp row base within tile
    int col_g = (wid & 1) * 64;      // warp col base within tile

    float acc[16][4];                // [mi*8+ni][d0..d3]
#pragma unroll
    for (int u = 0; u < 16; u++)
#pragma unroll
        for (int v = 0; v < 4; v++) acc[u][v] = 0.f;

    int li[2], lk4[2];
#pragma unroll
    for (int rep = 0; rep < 2; rep++) {
        int f4 = tid + rep * 256;
        li[rep]  = f4 >> 2;
        lk4[rep] = (f4 & 3) << 2;
    }

    float4 pa[2], pb[2];
#pragma unroll
    for (int rep = 0; rep < 2; rep++) {
        pa[rep] = make_float4(0.f, 0.f, 0.f, 0.f);
        pb[rep] = make_float4(0.f, 0.f, 0.f, 0.f);
        if (row0 + li[rep] < M)
            pa[rep] = *(const float4*)(P + (size_t)(row0 + li[rep]) * Nn + lk4[rep]);
        if (col0 + li[rep] < M)
            pb[rep] = *(const float4*)(P + (size_t)(col0 + li[rep]) * Nn + lk4[rep]);
    }

    for (int kk = 0; kk < 64; kk += 16) {
        __syncthreads();
#pragma unroll
        for (int rep = 0; rep < 2; rep++) {
            As[lk4[rep] + 0][li[rep]] = pa[rep].x;
            As[lk4[rep] + 1][li[rep]] = pa[rep].y;
            As[lk4[rep] + 2][li[rep]] = pa[rep].z;
            As[lk4[rep] + 3][li[rep]] = pa[rep].w;
            Bs[lk4[rep] + 0][li[rep]] = pb[rep].x;
            Bs[lk4[rep] + 1][li[rep]] = pb[rep].y;
            Bs[lk4[rep] + 2][li[rep]] = pb[rep].z;
            Bs[lk4[rep] + 3][li[rep]] = pb[rep].w;
        }
        __syncthreads();
        if (kk < 48) {
            int nk = kk + 16;
#pragma unroll
            for (int rep = 0; rep < 2; rep++) {
                pa[rep] = make_float4(0.f, 0.f, 0.f, 0.f);
                pb[rep] = make_float4(0.f, 0.f, 0.f, 0.f);
                if (row0 + li[rep] < M)
                    pa[rep] = *(const float4*)(P + (size_t)(row0 + li[rep]) * Nn + nk + lk4[rep]);
                if (col0 + li[rep] < M)
                    pb[rep] = *(const float4*)(P + (size_t)(col0 + li[rep]) * Nn + nk + lk4[rep]);
            }
        }
        // Two k8 MMA steps per 16-k chunk.
#pragma unroll
        for (int k8 = 0; k8 < 16; k8 += 8) {
            unsigned af[2][4];
#pragma unroll
            for (int mi = 0; mi < 2; mi++) {
                int rb = row_g + mi * 16;
                af[mi][0] = f2tf(As[k8 + tig][rb + gidx]);
                af[mi][1] = f2tf(As[k8 + tig][rb + 8 + gidx]);
                af[mi][2] = f2tf(As[k8 + 4 + tig][rb + gidx]);
                af[mi][3] = f2tf(As[k8 + 4 + tig][rb + 8 + gidx]);
            }
#pragma unroll
            for (int ni = 0; ni < 8; ni++) {
                unsigned b0 = f2tf(Bs[k8 + tig][col_g + ni * 8 + gidx]);
                unsigned b1 = f2tf(Bs[k8 + 4 + tig][col_g + ni * 8 + gidx]);
                mma_tf32(acc[ni],     af[0], b0, b1);
                mma_tf32(acc[8 + ni], af[1], b0, b1);
            }
        }
    }
    __syncthreads();

    // Write back: D-frag mapping d0:(g, 2t) d1:(g, 2t+1) d2:(g+8, 2t) d3:(g+8, 2t+1)
#pragma unroll
    for (int mi = 0; mi < 2; mi++) {
#pragma unroll
        for (int ni = 0; ni < 8; ni++) {
            float* d = acc[mi * 8 + ni];
            int r1 = row0 + row_g + mi * 16 + gidx;
            int r2 = r1 + 8;
            int c  = col0 + col_g + ni * 8 + tig * 2;
            if (by > bx) {
                if (r1 < M) {
                    float2 cv = *(float2*)(C + (size_t)r1 * Nn + c);
                    cv.x -= d[0]; cv.y -= d[1];
                    *(float2*)(C + (size_t)r1 * Nn + c) = cv;
                }
                if (r2 < M) {
                    float2 cv = *(float2*)(C + (size_t)r2 * Nn + c);
                    cv.x -= d[2]; cv.y -= d[3];
                    *(float2*)(C + (size_t)r2 * Nn + c) = cv;
                }
            } else {
                if (r1 < M) {
                    if (c     <= r1) C[(size_t)r1 * Nn + c]     -= d[0];
                    if (c + 1 <= r1) C[(size_t)r1 * Nn + c + 1] -= d[1];
                }
                if (r2 < M) {
                    if (c     <= r2) C[(size_t)r2 * Nn + c]     -= d[2];
                    if (c + 1 <= r2) C[(size_t)r2 * Nn + c + 1] -= d[3];
                }
            }
        }
    }
}

// map s (0-based) to lower-triangle tile (bx <= by): s = by(by+1)/2 + bx
__device__ __forceinline__ void tri_xy(int s, int& bx, int& by) {
    int byp = (int)((sqrtf(8.0f * (float)s + 1.0f) - 1.0f) * 0.5f);
    while ((byp + 1) * (byp + 2) / 2 <= s) byp++;
    while (byp * (byp + 1) / 2 > s) byp--;
    by = byp;
    bx = s - ((byp * (byp + 1)) >> 1);
}

// ================= THE WHOLE PROBLEM IN ONE PERSISTENT KERNEL =================
__global__ __launch_bounds__(256, 2) void fused_all(
    const float* __restrict__ us, const float* __restrict__ ut,
    const float* __restrict__ kf, const float* __restrict__ thrp,
    const float* __restrict__ iou, const float* __restrict__ W,
    const float* __restrict__ bb,
    float* __restrict__ Mp_out, float* __restrict__ flag_out,
    float* __restrict__ L)
{
    __shared__ float sbuf[2 * 16 * 136];   // 4352 floats; >= all phase needs
    int bid = blockIdx.x, G = gridDim.x, tid = threadIdx.x;
    int warp = tid >> 5, lane = tid & 31;

    // ---- P0: transpose ----
    for (int idx = bid * 256 + tid; idx < NSd * Dd; idx += G * 256) {
        int i = idx >> 9, d = idx & 511;
        g_e1[idx] = us[d * NSd + i];
        g_e2[idx] = ut[d * NSd + i];
    }
    grid_sync();

    // ---- P1: Mp0 = e1 e2^T + iou ----
    for (int i = bid; i < NSd; i += G) {
        const float* a = g_e1 + i * Dd;
        for (int jj = warp; jj < NSd; jj += 8) {
            const float* bptr = g_e2 + jj * Dd;
            float s = 0.f;
#pragma unroll 4
            for (int d = lane; d < Dd; d += 32) s += a[d] * bptr[d];
            s = warp_sum(s);
            if (lane == 0) g_Mp0[i * NSd + jj] = s + iou[i * NSd + jj];
        }
    }
    grid_sync();

    // ---- P2: m1 = Mp0 e2, m2 = Mp0^T e1 ----
    for (int t = bid; t < 2 * NSd; t += G) {
        int which = t >= NSd;
        int r = t - which * NSd;
        if (tid < NSd) sbuf[tid] = which ? g_Mp0[tid * NSd + r] : g_Mp0[r * NSd + tid];
        __syncthreads();
        const float* E = which ? g_e1 : g_e2;
        float* outp    = which ? g_m2 : g_m1;
        for (int d = tid; d < Dd; d += 256) {
            float acc = 0.f;
#pragma unroll 8
            for (int u = 0; u < NSd; u++) acc += sbuf[u] * E[u * Dd + d];
            outp[r * Dd + d] = acc;
        }
        __syncthreads();
    }
    grid_sync();

    // ---- P3: lam = ||e||/||m||; x = e + lam*m ----
    for (int t = bid; t < 2 * NSd; t += G) {
        int which = t >= NSd;
        int r = t - which * NSd;
        const float* e = (which ? g_e2 : g_e1) + r * Dd;
        const float* m = (which ? g_m2 : g_m1) + r * Dd;
        float* x       = (which ? g_x2 : g_x1) + r * Dd;
        float se = 0.f, sm = 0.f;
        for (int d = tid; d < Dd; d += 256) {
            float ev = e[d], mv = m[d];
            se += ev * ev; sm += mv * mv;
        }
        se = warp_sum(se); sm = warp_sum(sm);
        if (lane == 0) { sbuf[warp] = se; sbuf[8 + warp] = sm; }
        __syncthreads();
        if (tid == 0) {
            float SE = 0.f, SM = 0.f;
            for (int u = 0; u < 8; u++) { SE += sbuf[u]; SM += sbuf[8 + u]; }
            sbuf[16] = sqrtf(SE) / sqrtf(SM);
        }
        __syncthreads();
        float lam = sbuf[16];
        for (int d = tid; d < Dd; d += 256) x[d] = e[d] + lam * m[d];
        __syncthreads();
    }
    grid_sync();

    // ---- P4: y = relu(x W^T + b) ----
    for (int t = bid; t < 2 * NSd; t += G) {
        int which = t >= NSd;
        int r = t - which * NSd;
        const float* X = (which ? g_x2 : g_x1) + r * Dd;
        float* Y       = (which ? g_y2 : g_y1) + r * Dd;
        for (int d = tid; d < Dd; d += 256) sbuf[d] = X[d];
        __syncthreads();
        for (int o = warp; o < Dd; o += 8) {
            const float* wr = W + o * Dd;
            float s = 0.f;
#pragma unroll 4
            for (int d = lane; d < Dd; d += 32) s += sbuf[d] * wr[d];
            s = warp_sum(s);
            if (lane == 0) Y[o] = fmaxf(s + bb[o], 0.f);
        }
        __syncthreads();
    }
    grid_sync();

    // ---- P5: row l2 normalize ----
    for (int t = bid; t < 2 * NSd; t += G) {
        int which = t >= NSd;
        int r = t - which * NSd;
        float* y = (which ? g_y2 : g_y1) + r * Dd;
        float s = 0.f;
        for (int d = tid; d < Dd; d += 256) { float v = y[d]; s += v * v; }
        s = warp_sum(s);
        if (lane == 0) sbuf[warp] = s;
        __syncthreads();
        if (tid == 0) {
            float S = 0.f;
            for (int u = 0; u < 8; u++) S += sbuf[u];
            sbuf[8] = 1.0f / fmaxf(sqrtf(S), 1e-12f);
        }
        __syncthreads();
        float inv = sbuf[8];
        for (int d = tid; d < Dd; d += 256) y[d] *= inv;
        __syncthreads();
    }
    grid_sync();

    // ---- P6: Mp, thr_flag, v ----
    {
        float th = thrp[0];
        for (int i = bid; i < NSd; i += G) {
            const float* a = g_y1 + i * Dd;
            for (int jj = warp; jj < NSd; jj += 8) {
                const float* bptr = g_y2 + jj * Dd;
                float s = 0.f;
#pragma unroll 4
                for (int d = lane; d < Dd; d += 32) s += a[d] * bptr[d];
                s = warp_sum(s);
                if (lane == 0) {
                    Mp_out[i * NSd + jj] = s;
                    g_v[jj * NSd + i] = s;
                    float fl = (kf[i * NSd + jj] == -1.0f || iou[i * NSd + jj] == 0.0f || s < th) ? 1.0f : 0.0f;
                    flag_out[i * NSd + jj] = fl;
                }
            }
        }
    }
    grid_sync();

    // ---- P7: build A into L ----
    for (int p = bid; p < Nn; p += G) {
        int s1 = p % NSd, t1 = p / NSd;
        float vp = g_v[p];
        float* row = L + (size_t)p * Nn;
        for (int q = tid; q < Nn; q += 256) {
            float val = 0.f;
            if (q == p) val = 6241.0f;
            else if (q < p) {
                int s2 = q % NSd, t2 = q / NSd;
                if (s1 != s2 && t1 != t2) val = -0.5f * (vp + g_v[q]);
            }
            row[q] = val;
        }
    }
    grid_sync();

    // ---- P8: Cholesky (2 phases/step, fused fact64, tensor-core syrk) ----
    if (bid == 0) fact64(L, sbuf);
    grid_sync();

    for (int j = 0; j + 64 < Nn; j += 64) {
        int M  = Nn - j - 64;
        int nt64 = (M + 63) >> 6;                 // 64-row trsm tiles (<=99 => one wave)

        for (int t = bid; t < nt64; t += G)
            trsm64_tile(L, j, M, t << 6, sbuf);
        grid_sync();

        int nt  = (M + 127) >> 7;
        int ntS = nt * (nt + 1) / 2;
        if (bid == 0) {
            syrk_tile(L, j, M, 0, 0, sbuf);
            __syncthreads();
            fact64(L + (size_t)(j + 64) * Nn + (j + 64), sbuf);
        } else {
            for (int s = bid; s < ntS; s += G - 1) {
                int bx, by;
                tri_xy(s, bx, by);
                syrk_tile(L, j, M, bx, by, sbuf);
            }
        }
        grid_sync();
    }
}

// ---------------- launch ----------------
extern "C" void kernel_launch(void* const* d_in, const int* in_sizes, int n_in,
                              void* d_out, int out_size) {
    (void)in_sizes; (void)n_in; (void)out_size;
    const float* U_src = (const float*)d_in[0];
    const float* U_tgt = (const float*)d_in[1];
    const float* kf    = (const float*)d_in[2];
    const float* thrp  = (const float*)d_in[3];
    const float* iou   = (const float*)d_in[4];
    const float* W     = (const float*)d_in[5];
    const float* b     = (const float*)d_in[6];

    float* out      = (float*)d_out;
    float* Mp_out   = out;                       // [80*80]
    float* Lm       = out + NSd * NSd;           // [6400*6400]
    float* flag_out = out + NSd * NSd + Nn * Nn; // [80*80]

    fused_all<<<GPERS, 256>>>(U_src, U_tgt, kf, thrp, iou, W, b,
                              Mp_out, flag_out, Lm);
}